// round 3
// baseline (speedup 1.0000x reference)
#include <cuda_runtime.h>
#include <cuda_bf16.h>
#include <stdint.h>

typedef __nv_bfloat16 bf16;

#define NB 8
#define NT 2048
#define NC 512
#define NX (NB*NT*NC)          // 8388608 elements per (B,T,C) tensor
#define NW (NC*NC)             // 262144

// ---------------- scratch (static device globals; no runtime allocation) ----
__device__ __align__(128) bf16 g_xbl[NX];
__device__ __align__(128) bf16 g_xbr[NX];
__device__ __align__(128) bf16 g_wts[6*NW];
__device__ __align__(128) bf16 g_H[NX];
__device__ __align__(128) bf16 g_Ql[NX];
__device__ __align__(128) bf16 g_Qr[NX];
__device__ __align__(128) bf16 g_Vt[NX];
__device__ __align__(128) bf16 g_VlT[NX];             // (b, c, t)
__device__ __align__(128) bf16 g_VrT[NX];             // (b, c, t)
__device__ __align__(128) bf16 g_E [33554432];        // exp(scores), (b, t, s)
__device__ __align__(128) bf16 g_ET[33554432];        // transposed,  (b, s, t)
__device__ __align__(128) bf16 g_F1[NX];
__device__ __align__(128) bf16 g_F2[NX];
__device__ float g_rinv[NB*NT];
__device__ float g_cinv[NB*NT];

// ---------------- helpers ---------------------------------------------------
__device__ __forceinline__ float fexp_(float x){
    if (fabsf(x) < 0.25f){
        return 1.f + x*(1.f + x*(0.5f + x*(0.16666667f + x*0.04166667f)));
    }
    return __expf(x);
}

__device__ __forceinline__ void ldsm_x4(uint32_t addr, uint32_t& r0, uint32_t& r1,
                                        uint32_t& r2, uint32_t& r3){
    asm volatile("ldmatrix.sync.aligned.m8n8.x4.shared.b16 {%0,%1,%2,%3}, [%4];"
                 : "=r"(r0), "=r"(r1), "=r"(r2), "=r"(r3) : "r"(addr));
}

// ---------------- fp32 -> bf16 convert --------------------------------------
__global__ void k_f2bf(const float* __restrict__ in, bf16* __restrict__ out, int n){
    int i = (blockIdx.x * 256 + threadIdx.x) * 4;
    if (i + 3 < n){
        float4 v = *(const float4*)(in + i);
        *(__nv_bfloat162*)(out + i    ) = __floats2bfloat162_rn(v.x, v.y);
        *(__nv_bfloat162*)(out + i + 2) = __floats2bfloat162_rn(v.z, v.w);
    }
}

// ---------------- depthwise conv k=3 over T, per-batch zero pad -------------
__global__ void k_dw(const bf16* __restrict__ H, const float* __restrict__ w2,
                     const float* __restrict__ b2, bf16* __restrict__ out){
    int i = blockIdx.x * 256 + threadIdx.x;
    const int CP = NC / 2;
    int cp = i % CP;
    int t  = (i / CP) % NT;
    int b  = i / (CP * NT);
    int c  = cp * 2;
    size_t base = ((size_t)b * NT + t) * NC + c;
    float2 h0 = __bfloat1622float2(*(const __nv_bfloat162*)(H + base));
    float2 hm = make_float2(0.f, 0.f), hp = make_float2(0.f, 0.f);
    if (t > 0)      hm = __bfloat1622float2(*(const __nv_bfloat162*)(H + base - NC));
    if (t < NT - 1) hp = __bfloat1622float2(*(const __nv_bfloat162*)(H + base + NC));
    float o0 = hm.x * w2[c*3+0] + h0.x * w2[c*3+1] + hp.x * w2[c*3+2] + b2[c];
    float o1 = hm.y * w2[c*3+3] + h0.y * w2[c*3+4] + hp.y * w2[c*3+5] + b2[c+1];
    *(__nv_bfloat162*)(out + base) = __floats2bfloat162_rn(o0, o1);
}

// ---------------- tiled bf16 transpose: (z,R,C) -> (z,C,R) ------------------
__global__ void k_transpose(const bf16* __restrict__ in, bf16* __restrict__ out,
                            int R, int Cd){
    __shared__ bf16 ts[64][66];
    size_t base = (size_t)blockIdx.z * R * Cd;
    int r0 = blockIdx.y * 64, c0 = blockIdx.x * 64;
    #pragma unroll
    for (int it = 0; it < 2; it++){
        int q  = threadIdx.x + it * 256;
        int r  = q >> 3, c8 = (q & 7) * 8;
        uint4 v = *(const uint4*)(in + base + (size_t)(r0 + r) * Cd + c0 + c8);
        uint32_t* s = (uint32_t*)&ts[r][c8];
        s[0] = v.x; s[1] = v.y; s[2] = v.z; s[3] = v.w;
    }
    __syncthreads();
    #pragma unroll
    for (int it = 0; it < 8; it++){
        int p = threadIdx.x + it * 256;
        int c = p >> 5, r = (p & 31) * 2;
        __nv_bfloat162 v;
        v.x = ts[r][c]; v.y = ts[r + 1][c];
        *(__nv_bfloat162*)(out + base + (size_t)(c0 + c) * R + r0 + r) = v;
    }
}

// ---------------- row sum -> reciprocal -------------------------------------
__global__ void k_rowsum_inv(const bf16* __restrict__ E, float* __restrict__ inv, int L){
    size_t row = blockIdx.x;
    const __nv_bfloat162* p = (const __nv_bfloat162*)(E + row * (size_t)L);
    float s = 0.f;
    for (int i = threadIdx.x; i < L / 2; i += 256){
        float2 f = __bfloat1622float2(p[i]);
        s += f.x + f.y;
    }
    #pragma unroll
    for (int off = 16; off; off >>= 1) s += __shfl_xor_sync(0xffffffffu, s, off);
    __shared__ float sh[8];
    if ((threadIdx.x & 31) == 0) sh[threadIdx.x >> 5] = s;
    __syncthreads();
    if (threadIdx.x == 0){
        float t = 0.f;
        #pragma unroll
        for (int i = 0; i < 8; i++) t += sh[i];
        inv[row] = 1.0f / t;
    }
}

// ---------------- NT bf16 GEMM (mma.sync + ldmatrix) ------------------------
// C[m,n] = epi( sum_k A[m,k] * B[n,k] )
// EPI: 1 = +bias -> bf16 ; 2 = exp(alpha*acc) -> bf16 ;
//      3 = acc * rowscale[m] -> bf16 ; 4 = +bias + fp32 residual -> fp32
template<int EPI>
__global__ void __launch_bounds__(256, 2)
k_gemm_nt(const bf16* __restrict__ Ag, const bf16* __restrict__ Bg,
          void* __restrict__ Cg, int M, int N, int K,
          long long sA, long long sB, long long sC,
          const float* __restrict__ bias,
          const float* __restrict__ rowscale, int sRS,
          const float* __restrict__ resid, float alpha)
{
    __shared__ bf16 As[2][128][40];
    __shared__ bf16 Bs[2][128][40];
    const int tid = threadIdx.x;
    const int bz  = blockIdx.z;
    const bf16* A = Ag + (size_t)bz * sA;
    const bf16* B = Bg + (size_t)bz * sB;
    const int m0 = blockIdx.y * 128;
    const int n0 = blockIdx.x * 128;
    const int lrow = tid >> 2;
    const int lcol = (tid & 3) << 3;
    const int warp = tid >> 5, lane = tid & 31;
    const int wm = (warp & 1) << 6, wn = (warp >> 1) << 5;
    const int grp = lane >> 2, qid = lane & 3;

    // ldmatrix per-lane base addresses (bytes); row stride = 80B, stage = 10240B
    const uint32_t asb = (uint32_t)__cvta_generic_to_shared(&As[0][0][0]);
    const uint32_t bsb = (uint32_t)__cvta_generic_to_shared(&Bs[0][0][0]);
    const uint32_t aAddr0 = asb + (uint32_t)(wm + (lane & 15)) * 80u + (uint32_t)((lane >> 4) << 4);
    const uint32_t bAddr0 = bsb + (uint32_t)(wn + (lane & 7) + ((lane >> 4) << 3)) * 80u
                                + (uint32_t)(((lane >> 3) & 1) << 4);

    float acc[4][4][4];
    #pragma unroll
    for (int i = 0; i < 4; i++)
        #pragma unroll
        for (int j = 0; j < 4; j++)
            #pragma unroll
            for (int k = 0; k < 4; k++) acc[i][j][k] = 0.f;

    const int nt = K >> 5;

    auto load_stage = [&](int kt, int buf){
        const int k0 = kt << 5;
        #pragma unroll
        for (int h = 0; h < 2; h++){
            int r = lrow + (h << 6);
            const bf16* ga = A + (size_t)(m0 + r) * K + k0 + lcol;
            uint32_t sa = (uint32_t)__cvta_generic_to_shared(&As[buf][r][lcol]);
            asm volatile("cp.async.cg.shared.global [%0], [%1], 16;\n" :: "r"(sa), "l"(ga));
            const bf16* gb = B + (size_t)(n0 + r) * K + k0 + lcol;
            uint32_t sb = (uint32_t)__cvta_generic_to_shared(&Bs[buf][r][lcol]);
            asm volatile("cp.async.cg.shared.global [%0], [%1], 16;\n" :: "r"(sb), "l"(gb));
        }
        asm volatile("cp.async.commit_group;\n");
    };

    load_stage(0, 0);
    for (int kt = 0; kt < nt; kt++){
        int buf = kt & 1;
        if (kt + 1 < nt){
            load_stage(kt + 1, buf ^ 1);
            asm volatile("cp.async.wait_group 1;\n");
        } else {
            asm volatile("cp.async.wait_group 0;\n");
        }
        __syncthreads();
        const uint32_t aStage = aAddr0 + (uint32_t)buf * 10240u;
        const uint32_t bStage = bAddr0 + (uint32_t)buf * 10240u;
        #pragma unroll
        for (int ks = 0; ks < 2; ks++){
            const uint32_t kb = (uint32_t)(ks << 5);      // k offset in bytes (16 bf16)
            uint32_t af[4][4], bfg[4][2];
            #pragma unroll
            for (int mi = 0; mi < 4; mi++){
                ldsm_x4(aStage + (uint32_t)mi * 1280u + kb,
                        af[mi][0], af[mi][1], af[mi][2], af[mi][3]);
            }
            #pragma unroll
            for (int nj = 0; nj < 2; nj++){
                ldsm_x4(bStage + (uint32_t)nj * 1280u + kb,
                        bfg[2*nj][0], bfg[2*nj][1], bfg[2*nj+1][0], bfg[2*nj+1][1]);
            }
            #pragma unroll
            for (int mi = 0; mi < 4; mi++)
                #pragma unroll
                for (int ni = 0; ni < 4; ni++){
                    asm volatile(
                        "mma.sync.aligned.m16n8k16.row.col.f32.bf16.bf16.f32 "
                        "{%0,%1,%2,%3}, {%4,%5,%6,%7}, {%8,%9}, {%0,%1,%2,%3};\n"
                        : "+f"(acc[mi][ni][0]), "+f"(acc[mi][ni][1]),
                          "+f"(acc[mi][ni][2]), "+f"(acc[mi][ni][3])
                        : "r"(af[mi][0]), "r"(af[mi][1]), "r"(af[mi][2]), "r"(af[mi][3]),
                          "r"(bfg[ni][0]), "r"(bfg[ni][1]));
                }
        }
        __syncthreads();
    }

    #pragma unroll
    for (int mi = 0; mi < 4; mi++){
        #pragma unroll
        for (int ni = 0; ni < 4; ni++){
            int row = m0 + wm + (mi << 4) + grp;
            int col = n0 + wn + (ni << 3) + (qid << 1);
            float v0 = acc[mi][ni][0], v1 = acc[mi][ni][1];
            float v2 = acc[mi][ni][2], v3 = acc[mi][ni][3];
            if (EPI == 1){
                float b0 = bias[col], b1 = bias[col + 1];
                v0 += b0; v1 += b1; v2 += b0; v3 += b1;
            } else if (EPI == 2){
                v0 = fexp_(v0 * alpha); v1 = fexp_(v1 * alpha);
                v2 = fexp_(v2 * alpha); v3 = fexp_(v3 * alpha);
            } else if (EPI == 3){
                float r0 = rowscale[(size_t)bz * sRS + row];
                float r1 = rowscale[(size_t)bz * sRS + row + 8];
                v0 *= r0; v1 *= r0; v2 *= r1; v3 *= r1;
            } else if (EPI == 4){
                float b0 = bias[col], b1 = bias[col + 1];
                const float* R0 = resid + (size_t)row * N + col;
                const float* R1 = resid + (size_t)(row + 8) * N + col;
                v0 += b0 + R0[0]; v1 += b1 + R0[1];
                v2 += b0 + R1[0]; v3 += b1 + R1[1];
            }
            if (EPI == 4){
                float* C = (float*)Cg + (size_t)bz * sC;
                *(float2*)&C[(size_t)row * N + col]       = make_float2(v0, v1);
                *(float2*)&C[(size_t)(row + 8) * N + col] = make_float2(v2, v3);
            } else {
                bf16* C = (bf16*)Cg + (size_t)bz * sC;
                *(__nv_bfloat162*)&C[(size_t)row * N + col]       = __floats2bfloat162_rn(v0, v1);
                *(__nv_bfloat162*)&C[(size_t)(row + 8) * N + col] = __floats2bfloat162_rn(v2, v3);
            }
        }
    }
}

// ---------------- launcher --------------------------------------------------
extern "C" void kernel_launch(void* const* d_in, const int* in_sizes, int n_in,
                              void* d_out, int out_size){
    (void)in_sizes; (void)n_in; (void)out_size;
    const float* x_l    = (const float*)d_in[0];
    const float* x_r    = (const float*)d_in[1];
    const float* lp1_w1 = (const float*)d_in[2];
    const float* lp1_b1 = (const float*)d_in[3];
    const float* lp1_w2 = (const float*)d_in[4];
    const float* lp1_b2 = (const float*)d_in[5];
    const float* rp1_w1 = (const float*)d_in[6];
    const float* rp1_b1 = (const float*)d_in[7];
    const float* rp1_w2 = (const float*)d_in[8];
    const float* rp1_b2 = (const float*)d_in[9];
    const float* lp2_w1 = (const float*)d_in[10];
    const float* lp2_b1 = (const float*)d_in[11];
    const float* lp2_w2 = (const float*)d_in[12];
    const float* lp2_b2 = (const float*)d_in[13];
    const float* rp2_w1 = (const float*)d_in[14];
    const float* rp2_b1 = (const float*)d_in[15];
    const float* rp2_w2 = (const float*)d_in[16];
    const float* rp2_b2 = (const float*)d_in[17];
    const float* lp3_w  = (const float*)d_in[18];
    const float* lp3_b  = (const float*)d_in[19];
    const float* rp3_w  = (const float*)d_in[20];
    const float* rp3_b  = (const float*)d_in[21];

    bf16 *xbl, *xbr, *w, *H, *Ql, *Qr, *Vt, *VlT, *VrT, *E, *ET, *F1, *F2;
    float *rinv, *cinv;
    cudaGetSymbolAddress((void**)&xbl, g_xbl);
    cudaGetSymbolAddress((void**)&xbr, g_xbr);
    cudaGetSymbolAddress((void**)&w,   g_wts);
    cudaGetSymbolAddress((void**)&H,   g_H);
    cudaGetSymbolAddress((void**)&Ql,  g_Ql);
    cudaGetSymbolAddress((void**)&Qr,  g_Qr);
    cudaGetSymbolAddress((void**)&Vt,  g_Vt);
    cudaGetSymbolAddress((void**)&VlT, g_VlT);
    cudaGetSymbolAddress((void**)&VrT, g_VrT);
    cudaGetSymbolAddress((void**)&E,   g_E);
    cudaGetSymbolAddress((void**)&ET,  g_ET);
    cudaGetSymbolAddress((void**)&F1,  g_F1);
    cudaGetSymbolAddress((void**)&F2,  g_F2);
    cudaGetSymbolAddress((void**)&rinv, g_rinv);
    cudaGetSymbolAddress((void**)&cinv, g_cinv);

    const int nx = NX, nw = NW;
    const float scale = 0.04419417382415922f;   // 512^-0.5

    k_f2bf<<<nx/1024, 256>>>(x_l, xbl, nx);
    k_f2bf<<<nx/1024, 256>>>(x_r, xbr, nx);
    k_f2bf<<<nw/1024, 256>>>(lp1_w1, w + 0*nw, nw);
    k_f2bf<<<nw/1024, 256>>>(rp1_w1, w + 1*nw, nw);
    k_f2bf<<<nw/1024, 256>>>(lp2_w1, w + 2*nw, nw);
    k_f2bf<<<nw/1024, 256>>>(rp2_w1, w + 3*nw, nw);
    k_f2bf<<<nw/1024, 256>>>(lp3_w,  w + 4*nw, nw);
    k_f2bf<<<nw/1024, 256>>>(rp3_w,  w + 5*nw, nw);

    dim3 blk(256);
    dim3 gP(NC/128, (NB*NT)/128, 1);     // (4,128,1)
    dim3 gA(NT/128, NT/128, NB);         // (16,16,8)
    dim3 gF(NC/128, NT/128, NB);         // (4,16,8)
    dim3 gTv(NC/64, NT/64, NB);
    dim3 gTe(NT/64, NT/64, NB);
    const int dwBlocks = (NX/2)/256;

    // projections -> Q_l, Q_r, V_lT, V_rT
    k_gemm_nt<1><<<gP, blk>>>(xbl, w + 0*nw, H, NB*NT, NC, NC, 0,0,0, lp1_b1, nullptr,0, nullptr, 0.f);
    k_dw<<<dwBlocks, 256>>>(H, lp1_w2, lp1_b2, Ql);
    k_gemm_nt<1><<<gP, blk>>>(xbr, w + 1*nw, H, NB*NT, NC, NC, 0,0,0, rp1_b1, nullptr,0, nullptr, 0.f);
    k_dw<<<dwBlocks, 256>>>(H, rp1_w2, rp1_b2, Qr);
    k_gemm_nt<1><<<gP, blk>>>(xbl, w + 2*nw, H, NB*NT, NC, NC, 0,0,0, lp2_b1, nullptr,0, nullptr, 0.f);
    k_dw<<<dwBlocks, 256>>>(H, lp2_w2, lp2_b2, Vt);
    k_transpose<<<gTv, 256>>>(Vt, VlT, NT, NC);
    k_gemm_nt<1><<<gP, blk>>>(xbr, w + 3*nw, H, NB*NT, NC, NC, 0,0,0, rp2_b1, nullptr,0, nullptr, 0.f);
    k_dw<<<dwBlocks, 256>>>(H, rp2_w2, rp2_b2, Vt);
    k_transpose<<<gTv, 256>>>(Vt, VrT, NT, NC);

    // E = exp(scale * Q_l Q_r^T)
    k_gemm_nt<2><<<gA, blk>>>(Ql, Qr, E, NT, NT, NC,
                              (long long)NT*NC, (long long)NT*NC, (long long)NT*NT,
                              nullptr, nullptr, 0, nullptr, scale);

    // softmax denominators
    k_rowsum_inv<<<NB*NT, 256>>>(E, rinv, NT);
    k_transpose<<<gTe, 256>>>(E, ET, NT, NT);
    k_rowsum_inv<<<NB*NT, 256>>>(ET, cinv, NT);

    // attention applies (normalization folded into epilogue)
    k_gemm_nt<3><<<gF, blk>>>(E, VrT, F1, NT, NC, NT,
                              (long long)NT*NT, (long long)NC*NT, (long long)NT*NC,
                              nullptr, rinv, NT, nullptr, 0.f);
    k_gemm_nt<3><<<gF, blk>>>(ET, VlT, F2, NT, NC, NT,
                              (long long)NT*NT, (long long)NC*NT, (long long)NT*NC,
                              nullptr, cinv, NT, nullptr, 0.f);

    // output projections + residual -> fp32 out
    float* out = (float*)d_out;
    k_gemm_nt<4><<<gP, blk>>>(F1, w + 4*nw, out,      NB*NT, NC, NC, 0,0,0, lp3_b, nullptr,0, x_l, 0.f);
    k_gemm_nt<4><<<gP, blk>>>(F2, w + 5*nw, out + nx, NB*NT, NC, NC, 0,0,0, rp3_b, nullptr,0, x_r, 0.f);
}

// round 4
// speedup vs baseline: 1.4182x; 1.4182x over previous
#include <cuda_runtime.h>
#include <cuda_bf16.h>
#include <stdint.h>

typedef __nv_bfloat16 bf16;

#define NB 8
#define NT 2048
#define NC 512
#define NX (NB*NT*NC)
#define NW (NC*NC)

// ---------------- scratch ----------------------------------------------------
__device__ __align__(128) bf16 g_xbl[NX];
__device__ __align__(128) bf16 g_xbr[NX];
__device__ __align__(128) bf16 g_wts[6*NW];
__device__ __align__(128) bf16 g_H[NX];
__device__ __align__(128) bf16 g_Ql[NX];
__device__ __align__(128) bf16 g_Qr[NX];
__device__ __align__(128) bf16 g_Vt[NX];
__device__ __align__(128) bf16 g_VlT[NX];
__device__ __align__(128) bf16 g_VrT[NX];
__device__ __align__(128) bf16 g_E [33554432];
__device__ __align__(128) bf16 g_ET[33554432];
__device__ __align__(128) bf16 g_F1[NX];
__device__ __align__(128) bf16 g_F2[NX];
__device__ float g_rinv[NB*NT];
__device__ float g_cinv[NB*NT];

// ---------------- helpers ---------------------------------------------------
__device__ __forceinline__ float fexp_(float x){
    if (fabsf(x) < 0.25f){
        return 1.f + x*(1.f + x*(0.5f + x*(0.16666667f + x*0.04166667f)));
    }
    return __expf(x);
}

// ---------------- fp32 -> bf16 convert --------------------------------------
__global__ void k_f2bf(const float* __restrict__ in, bf16* __restrict__ out, int n){
    int i = (blockIdx.x * 256 + threadIdx.x) * 4;
    if (i + 3 < n){
        float4 v = *(const float4*)(in + i);
        *(__nv_bfloat162*)(out + i    ) = __floats2bfloat162_rn(v.x, v.y);
        *(__nv_bfloat162*)(out + i + 2) = __floats2bfloat162_rn(v.z, v.w);
    }
}

// ---------------- depthwise conv k=3 over T ---------------------------------
__global__ void k_dw(const bf16* __restrict__ H, const float* __restrict__ w2,
                     const float* __restrict__ b2, bf16* __restrict__ out){
    int i = blockIdx.x * 256 + threadIdx.x;
    const int CP = NC / 2;
    int cp = i % CP;
    int t  = (i / CP) % NT;
    int b  = i / (CP * NT);
    int c  = cp * 2;
    size_t base = ((size_t)b * NT + t) * NC + c;
    float2 h0 = __bfloat1622float2(*(const __nv_bfloat162*)(H + base));
    float2 hm = make_float2(0.f, 0.f), hp = make_float2(0.f, 0.f);
    if (t > 0)      hm = __bfloat1622float2(*(const __nv_bfloat162*)(H + base - NC));
    if (t < NT - 1) hp = __bfloat1622float2(*(const __nv_bfloat162*)(H + base + NC));
    float o0 = hm.x * w2[c*3+0] + h0.x * w2[c*3+1] + hp.x * w2[c*3+2] + b2[c];
    float o1 = hm.y * w2[c*3+3] + h0.y * w2[c*3+4] + hp.y * w2[c*3+5] + b2[c+1];
    *(__nv_bfloat162*)(out + base) = __floats2bfloat162_rn(o0, o1);
}

// ---------------- tiled bf16 transpose: (z,R,C) -> (z,C,R) ------------------
__global__ void k_transpose(const bf16* __restrict__ in, bf16* __restrict__ out,
                            int R, int Cd){
    __shared__ bf16 ts[64][66];
    size_t base = (size_t)blockIdx.z * R * Cd;
    int r0 = blockIdx.y * 64, c0 = blockIdx.x * 64;
    #pragma unroll
    for (int it = 0; it < 2; it++){
        int q  = threadIdx.x + it * 256;
        int r  = q >> 3, c8 = (q & 7) * 8;
        uint4 v = *(const uint4*)(in + base + (size_t)(r0 + r) * Cd + c0 + c8);
        uint32_t* s = (uint32_t*)&ts[r][c8];
        s[0] = v.x; s[1] = v.y; s[2] = v.z; s[3] = v.w;
    }
    __syncthreads();
    #pragma unroll
    for (int it = 0; it < 8; it++){
        int p = threadIdx.x + it * 256;
        int c = p >> 5, r = (p & 31) * 2;
        __nv_bfloat162 v;
        v.x = ts[r][c]; v.y = ts[r + 1][c];
        *(__nv_bfloat162*)(out + base + (size_t)(c0 + c) * R + r0 + r) = v;
    }
}

// ---------------- row sum -> reciprocal -------------------------------------
__global__ void k_rowsum_inv(const bf16* __restrict__ E, float* __restrict__ inv, int L){
    size_t row = blockIdx.x;
    const __nv_bfloat162* p = (const __nv_bfloat162*)(E + row * (size_t)L);
    float s = 0.f;
    for (int i = threadIdx.x; i < L / 2; i += 256){
        float2 f = __bfloat1622float2(p[i]);
        s += f.x + f.y;
    }
    #pragma unroll
    for (int off = 16; off; off >>= 1) s += __shfl_xor_sync(0xffffffffu, s, off);
    __shared__ float sh[8];
    if ((threadIdx.x & 31) == 0) sh[threadIdx.x >> 5] = s;
    __syncthreads();
    if (threadIdx.x == 0){
        float t = 0.f;
        #pragma unroll
        for (int i = 0; i < 8; i++) t += sh[i];
        inv[row] = 1.0f / t;
    }
}

// ---------------- NT bf16 GEMM: 128x256 CTA tile, 64x64 warp tile -----------
// C[m,n] = epi( sum_k A[m,k] * B[n,k] )
// 3-stage cp.async ring, one __syncthreads per K-iteration.
// EPI: 1 = +bias -> bf16 ; 2 = exp(alpha*acc) -> bf16 ;
//      3 = acc * rowscale[m] -> bf16 ; 4 = +bias + fp32 residual -> fp32
#define STAGE_ELEMS 15360            // (128+256)*40 bf16 per stage
#define GSMEM_BYTES (3*STAGE_ELEMS*2)   // 92160 B

template<int EPI>
__global__ void __launch_bounds__(256)
k_gemm_nt(const bf16* __restrict__ Ag, const bf16* __restrict__ Bg,
          void* __restrict__ Cg, int M, int N, int K,
          long long sA, long long sB, long long sC,
          const float* __restrict__ bias,
          const float* __restrict__ rowscale, int sRS,
          const float* __restrict__ resid, float alpha)
{
    extern __shared__ bf16 dsm[];
    const int tid = threadIdx.x;
    const int bz  = blockIdx.z;
    const bf16* A = Ag + (size_t)bz * sA;
    const bf16* B = Bg + (size_t)bz * sB;
    const int m0 = blockIdx.y * 128;
    const int n0 = blockIdx.x * 256;
    const int lrow = tid >> 2;            // 0..63
    const int lcol = (tid & 3) << 3;      // 0,8,16,24
    const int warp = tid >> 5, lane = tid & 31;
    const int wm = (warp & 1) << 6;       // 0 / 64
    const int wn = (warp >> 1) << 6;      // 0 / 64 / 128 / 192
    const int grp = lane >> 2, qid = lane & 3;

    float acc[4][8][4];
    #pragma unroll
    for (int i = 0; i < 4; i++)
        #pragma unroll
        for (int j = 0; j < 8; j++)
            #pragma unroll
            for (int k = 0; k < 4; k++) acc[i][j][k] = 0.f;

    const int nkt = K >> 5;

    auto load_stage = [&](int kt, int s){
        const int k0 = kt << 5;
        bf16* as_ = dsm + s * STAGE_ELEMS;
        bf16* bs_ = as_ + 5120;
        #pragma unroll
        for (int h = 0; h < 2; h++){
            int r = lrow + (h << 6);
            const bf16* ga = A + (size_t)(m0 + r) * K + k0 + lcol;
            uint32_t sa = (uint32_t)__cvta_generic_to_shared(&as_[r * 40 + lcol]);
            asm volatile("cp.async.cg.shared.global [%0], [%1], 16;\n" :: "r"(sa), "l"(ga));
        }
        #pragma unroll
        for (int h = 0; h < 4; h++){
            int r = lrow + (h << 6);
            const bf16* gb = B + (size_t)(n0 + r) * K + k0 + lcol;
            uint32_t sb = (uint32_t)__cvta_generic_to_shared(&bs_[r * 40 + lcol]);
            asm volatile("cp.async.cg.shared.global [%0], [%1], 16;\n" :: "r"(sb), "l"(gb));
        }
        asm volatile("cp.async.commit_group;\n");
    };

    load_stage(0, 0);
    if (nkt > 1) load_stage(1, 1);

    for (int kt = 0; kt < nkt; kt++){
        const int s = kt % 3;
        if (kt + 1 < nkt) asm volatile("cp.async.wait_group 1;\n");
        else              asm volatile("cp.async.wait_group 0;\n");
        __syncthreads();
        if (kt + 2 < nkt) load_stage(kt + 2, (kt + 2) % 3);

        const bf16* as_ = dsm + s * STAGE_ELEMS;
        const bf16* bs_ = as_ + 5120;
        #pragma unroll
        for (int ks = 0; ks < 2; ks++){
            const int kk = (ks << 4) + (qid << 1);
            uint32_t af[4][4];
            #pragma unroll
            for (int mi = 0; mi < 4; mi++){
                int r = wm + (mi << 4) + grp;
                af[mi][0] = *(const uint32_t*)&as_[ r      * 40 + kk];
                af[mi][1] = *(const uint32_t*)&as_[(r + 8) * 40 + kk];
                af[mi][2] = *(const uint32_t*)&as_[ r      * 40 + kk + 8];
                af[mi][3] = *(const uint32_t*)&as_[(r + 8) * 40 + kk + 8];
            }
            #pragma unroll
            for (int nj = 0; nj < 8; nj++){
                int r = wn + (nj << 3) + grp;
                uint32_t b0 = *(const uint32_t*)&bs_[r * 40 + kk];
                uint32_t b1 = *(const uint32_t*)&bs_[r * 40 + kk + 8];
                #pragma unroll
                for (int mi = 0; mi < 4; mi++){
                    asm volatile(
                        "mma.sync.aligned.m16n8k16.row.col.f32.bf16.bf16.f32 "
                        "{%0,%1,%2,%3}, {%4,%5,%6,%7}, {%8,%9}, {%0,%1,%2,%3};\n"
                        : "+f"(acc[mi][nj][0]), "+f"(acc[mi][nj][1]),
                          "+f"(acc[mi][nj][2]), "+f"(acc[mi][nj][3])
                        : "r"(af[mi][0]), "r"(af[mi][1]), "r"(af[mi][2]), "r"(af[mi][3]),
                          "r"(b0), "r"(b1));
                }
            }
        }
    }

    #pragma unroll
    for (int mi = 0; mi < 4; mi++){
        #pragma unroll
        for (int nj = 0; nj < 8; nj++){
            int row = m0 + wm + (mi << 4) + grp;
            int col = n0 + wn + (nj << 3) + (qid << 1);
            float v0 = acc[mi][nj][0], v1 = acc[mi][nj][1];
            float v2 = acc[mi][nj][2], v3 = acc[mi][nj][3];
            if (EPI == 1){
                float b0 = bias[col], b1 = bias[col + 1];
                v0 += b0; v1 += b1; v2 += b0; v3 += b1;
            } else if (EPI == 2){
                v0 = fexp_(v0 * alpha); v1 = fexp_(v1 * alpha);
                v2 = fexp_(v2 * alpha); v3 = fexp_(v3 * alpha);
            } else if (EPI == 3){
                float r0 = rowscale[(size_t)bz * sRS + row];
                float r1 = rowscale[(size_t)bz * sRS + row + 8];
                v0 *= r0; v1 *= r0; v2 *= r1; v3 *= r1;
            } else if (EPI == 4){
                float b0 = bias[col], b1 = bias[col + 1];
                const float* R0 = resid + (size_t)row * N + col;
                const float* R1 = resid + (size_t)(row + 8) * N + col;
                v0 += b0 + R0[0]; v1 += b1 + R0[1];
                v2 += b0 + R1[0]; v3 += b1 + R1[1];
            }
            if (EPI == 4){
                float* C = (float*)Cg + (size_t)bz * sC;
                *(float2*)&C[(size_t)row * N + col]       = make_float2(v0, v1);
                *(float2*)&C[(size_t)(row + 8) * N + col] = make_float2(v2, v3);
            } else {
                bf16* C = (bf16*)Cg + (size_t)bz * sC;
                *(__nv_bfloat162*)&C[(size_t)row * N + col]       = __floats2bfloat162_rn(v0, v1);
                *(__nv_bfloat162*)&C[(size_t)(row + 8) * N + col] = __floats2bfloat162_rn(v2, v3);
            }
        }
    }
}

// ---------------- launcher --------------------------------------------------
extern "C" void kernel_launch(void* const* d_in, const int* in_sizes, int n_in,
                              void* d_out, int out_size){
    (void)in_sizes; (void)n_in; (void)out_size;
    const float* x_l    = (const float*)d_in[0];
    const float* x_r    = (const float*)d_in[1];
    const float* lp1_w1 = (const float*)d_in[2];
    const float* lp1_b1 = (const float*)d_in[3];
    const float* lp1_w2 = (const float*)d_in[4];
    const float* lp1_b2 = (const float*)d_in[5];
    const float* rp1_w1 = (const float*)d_in[6];
    const float* rp1_b1 = (const float*)d_in[7];
    const float* rp1_w2 = (const float*)d_in[8];
    const float* rp1_b2 = (const float*)d_in[9];
    const float* lp2_w1 = (const float*)d_in[10];
    const float* lp2_b1 = (const float*)d_in[11];
    const float* lp2_w2 = (const float*)d_in[12];
    const float* lp2_b2 = (const float*)d_in[13];
    const float* rp2_w1 = (const float*)d_in[14];
    const float* rp2_b1 = (const float*)d_in[15];
    const float* rp2_w2 = (const float*)d_in[16];
    const float* rp2_b2 = (const float*)d_in[17];
    const float* lp3_w  = (const float*)d_in[18];
    const float* lp3_b  = (const float*)d_in[19];
    const float* rp3_w  = (const float*)d_in[20];
    const float* rp3_b  = (const float*)d_in[21];

    bf16 *xbl, *xbr, *w, *H, *Ql, *Qr, *Vt, *VlT, *VrT, *E, *ET, *F1, *F2;
    float *rinv, *cinv;
    cudaGetSymbolAddress((void**)&xbl, g_xbl);
    cudaGetSymbolAddress((void**)&xbr, g_xbr);
    cudaGetSymbolAddress((void**)&w,   g_wts);
    cudaGetSymbolAddress((void**)&H,   g_H);
    cudaGetSymbolAddress((void**)&Ql,  g_Ql);
    cudaGetSymbolAddress((void**)&Qr,  g_Qr);
    cudaGetSymbolAddress((void**)&Vt,  g_Vt);
    cudaGetSymbolAddress((void**)&VlT, g_VlT);
    cudaGetSymbolAddress((void**)&VrT, g_VrT);
    cudaGetSymbolAddress((void**)&E,   g_E);
    cudaGetSymbolAddress((void**)&ET,  g_ET);
    cudaGetSymbolAddress((void**)&F1,  g_F1);
    cudaGetSymbolAddress((void**)&F2,  g_F2);
    cudaGetSymbolAddress((void**)&rinv, g_rinv);
    cudaGetSymbolAddress((void**)&cinv, g_cinv);

    cudaFuncSetAttribute(k_gemm_nt<1>, cudaFuncAttributeMaxDynamicSharedMemorySize, GSMEM_BYTES);
    cudaFuncSetAttribute(k_gemm_nt<2>, cudaFuncAttributeMaxDynamicSharedMemorySize, GSMEM_BYTES);
    cudaFuncSetAttribute(k_gemm_nt<3>, cudaFuncAttributeMaxDynamicSharedMemorySize, GSMEM_BYTES);
    cudaFuncSetAttribute(k_gemm_nt<4>, cudaFuncAttributeMaxDynamicSharedMemorySize, GSMEM_BYTES);

    const int nx = NX, nw = NW;
    const float scale = 0.04419417382415922f;   // 512^-0.5

    k_f2bf<<<nx/1024, 256>>>(x_l, xbl, nx);
    k_f2bf<<<nx/1024, 256>>>(x_r, xbr, nx);
    k_f2bf<<<nw/1024, 256>>>(lp1_w1, w + 0*nw, nw);
    k_f2bf<<<nw/1024, 256>>>(rp1_w1, w + 1*nw, nw);
    k_f2bf<<<nw/1024, 256>>>(lp2_w1, w + 2*nw, nw);
    k_f2bf<<<nw/1024, 256>>>(rp2_w1, w + 3*nw, nw);
    k_f2bf<<<nw/1024, 256>>>(lp3_w,  w + 4*nw, nw);
    k_f2bf<<<nw/1024, 256>>>(rp3_w,  w + 5*nw, nw);

    dim3 blk(256);
    dim3 gP(NC/256, (NB*NT)/128, 1);     // (2,128,1)
    dim3 gA(NT/256, NT/128, NB);         // (8,16,8)
    dim3 gF(NC/256, NT/128, NB);         // (2,16,8)
    dim3 gTv(NC/64, NT/64, NB);
    dim3 gTe(NT/64, NT/64, NB);
    const int dwBlocks = (NX/2)/256;

    // projections -> Q_l, Q_r, V_lT, V_rT
    k_gemm_nt<1><<<gP, blk, GSMEM_BYTES>>>(xbl, w + 0*nw, H, NB*NT, NC, NC, 0,0,0, lp1_b1, nullptr,0, nullptr, 0.f);
    k_dw<<<dwBlocks, 256>>>(H, lp1_w2, lp1_b2, Ql);
    k_gemm_nt<1><<<gP, blk, GSMEM_BYTES>>>(xbr, w + 1*nw, H, NB*NT, NC, NC, 0,0,0, rp1_b1, nullptr,0, nullptr, 0.f);
    k_dw<<<dwBlocks, 256>>>(H, rp1_w2, rp1_b2, Qr);
    k_gemm_nt<1><<<gP, blk, GSMEM_BYTES>>>(xbl, w + 2*nw, H, NB*NT, NC, NC, 0,0,0, lp2_b1, nullptr,0, nullptr, 0.f);
    k_dw<<<dwBlocks, 256>>>(H, lp2_w2, lp2_b2, Vt);
    k_transpose<<<gTv, 256>>>(Vt, VlT, NT, NC);
    k_gemm_nt<1><<<gP, blk, GSMEM_BYTES>>>(xbr, w + 3*nw, H, NB*NT, NC, NC, 0,0,0, rp2_b1, nullptr,0, nullptr, 0.f);
    k_dw<<<dwBlocks, 256>>>(H, rp2_w2, rp2_b2, Vt);
    k_transpose<<<gTv, 256>>>(Vt, VrT, NT, NC);

    // E = exp(scale * Q_l Q_r^T)
    k_gemm_nt<2><<<gA, blk, GSMEM_BYTES>>>(Ql, Qr, E, NT, NT, NC,
                              (long long)NT*NC, (long long)NT*NC, (long long)NT*NT,
                              nullptr, nullptr, 0, nullptr, scale);

    // softmax denominators
    k_rowsum_inv<<<NB*NT, 256>>>(E, rinv, NT);
    k_transpose<<<gTe, 256>>>(E, ET, NT, NT);
    k_rowsum_inv<<<NB*NT, 256>>>(ET, cinv, NT);

    // attention applies (normalization folded into epilogue)
    k_gemm_nt<3><<<gF, blk, GSMEM_BYTES>>>(E, VrT, F1, NT, NC, NT,
                              (long long)NT*NT, (long long)NC*NT, (long long)NT*NC,
                              nullptr, rinv, NT, nullptr, 0.f);
    k_gemm_nt<3><<<gF, blk, GSMEM_BYTES>>>(ET, VlT, F2, NT, NC, NT,
                              (long long)NT*NT, (long long)NC*NT, (long long)NT*NC,
                              nullptr, cinv, NT, nullptr, 0.f);

    // output projections + residual -> fp32 out
    float* out = (float*)d_out;
    k_gemm_nt<4><<<gP, blk, GSMEM_BYTES>>>(F1, w + 4*nw, out,      NB*NT, NC, NC, 0,0,0, lp3_b, nullptr,0, x_l, 0.f);
    k_gemm_nt<4><<<gP, blk, GSMEM_BYTES>>>(F2, w + 5*nw, out + nx, NB*NT, NC, NC, 0,0,0, rp3_b, nullptr,0, x_r, 0.f);
}

// round 5
// speedup vs baseline: 1.6328x; 1.1513x over previous
#include <cuda_runtime.h>
#include <cuda_fp16.h>
#include <stdint.h>

typedef __half f16;

#define NB 8
#define NT 2048
#define NC 512
#define NX (NB*NT*NC)
#define NW (NC*NC)

// ---------------- scratch ----------------------------------------------------
__device__ __align__(128) f16 g_xhl[NX];
__device__ __align__(128) f16 g_xhr[NX];
__device__ __align__(128) f16 g_wts[6*NW];
__device__ __align__(128) f16 g_H[NX];
__device__ __align__(128) f16 g_Ql[NX];
__device__ __align__(128) f16 g_Qr[NX];
__device__ __align__(128) f16 g_Vt[NX];
__device__ __align__(128) f16 g_VlT[NX];
__device__ __align__(128) f16 g_VrT[NX];
__device__ __align__(128) f16 g_E [33554432];
__device__ __align__(128) f16 g_ET[33554432];
__device__ __align__(128) f16 g_F1[NX];
__device__ __align__(128) f16 g_F2[NX];
__device__ float g_rinv[NB*NT];
__device__ float g_cinv[NB*NT];

// ---------------- helpers ---------------------------------------------------
__device__ __forceinline__ float fexp_(float x){
    if (fabsf(x) < 0.25f){
        return 1.f + x*(1.f + x*(0.5f + x*(0.16666667f + x*0.04166667f)));
    }
    return __expf(x);
}

// ---------------- fp32 -> fp16 convert --------------------------------------
__global__ void k_f2h(const float* __restrict__ in, f16* __restrict__ out, int n){
    int i = (blockIdx.x * 256 + threadIdx.x) * 4;
    if (i + 3 < n){
        float4 v = *(const float4*)(in + i);
        *(__half2*)(out + i    ) = __floats2half2_rn(v.x, v.y);
        *(__half2*)(out + i + 2) = __floats2half2_rn(v.z, v.w);
    }
}

// ---------------- depthwise conv k=3 over T ---------------------------------
__global__ void k_dw(const f16* __restrict__ H, const float* __restrict__ w2,
                     const float* __restrict__ b2, f16* __restrict__ out){
    int i = blockIdx.x * 256 + threadIdx.x;
    const int CP = NC / 2;
    int cp = i % CP;
    int t  = (i / CP) % NT;
    int b  = i / (CP * NT);
    int c  = cp * 2;
    size_t base = ((size_t)b * NT + t) * NC + c;
    float2 h0 = __half22float2(*(const __half2*)(H + base));
    float2 hm = make_float2(0.f, 0.f), hp = make_float2(0.f, 0.f);
    if (t > 0)      hm = __half22float2(*(const __half2*)(H + base - NC));
    if (t < NT - 1) hp = __half22float2(*(const __half2*)(H + base + NC));
    float o0 = hm.x * w2[c*3+0] + h0.x * w2[c*3+1] + hp.x * w2[c*3+2] + b2[c];
    float o1 = hm.y * w2[c*3+3] + h0.y * w2[c*3+4] + hp.y * w2[c*3+5] + b2[c+1];
    *(__half2*)(out + base) = __floats2half2_rn(o0, o1);
}

// ---------------- tiled f16 transpose: (z,R,C) -> (z,C,R) -------------------
__global__ void k_transpose(const f16* __restrict__ in, f16* __restrict__ out,
                            int R, int Cd){
    __shared__ f16 ts[64][66];
    size_t base = (size_t)blockIdx.z * R * Cd;
    int r0 = blockIdx.y * 64, c0 = blockIdx.x * 64;
    #pragma unroll
    for (int it = 0; it < 2; it++){
        int q  = threadIdx.x + it * 256;
        int r  = q >> 3, c8 = (q & 7) * 8;
        uint4 v = *(const uint4*)(in + base + (size_t)(r0 + r) * Cd + c0 + c8);
        uint32_t* s = (uint32_t*)&ts[r][c8];
        s[0] = v.x; s[1] = v.y; s[2] = v.z; s[3] = v.w;
    }
    __syncthreads();
    #pragma unroll
    for (int it = 0; it < 8; it++){
        int p = threadIdx.x + it * 256;
        int c = p >> 5, r = (p & 31) * 2;
        __half2 v;
        v.x = ts[r][c]; v.y = ts[r + 1][c];
        *(__half2*)(out + base + (size_t)(c0 + c) * R + r0 + r) = v;
    }
}

// ---------------- row sum -> reciprocal -------------------------------------
__global__ void k_rowsum_inv(const f16* __restrict__ E, float* __restrict__ inv, int L){
    size_t row = blockIdx.x;
    const __half2* p = (const __half2*)(E + row * (size_t)L);
    float s = 0.f;
    for (int i = threadIdx.x; i < L / 2; i += 256){
        float2 f = __half22float2(p[i]);
        s += f.x + f.y;
    }
    #pragma unroll
    for (int off = 16; off; off >>= 1) s += __shfl_xor_sync(0xffffffffu, s, off);
    __shared__ float sh[8];
    if ((threadIdx.x & 31) == 0) sh[threadIdx.x >> 5] = s;
    __syncthreads();
    if (threadIdx.x == 0){
        float t = 0.f;
        #pragma unroll
        for (int i = 0; i < 8; i++) t += sh[i];
        inv[row] = 1.0f / t;
    }
}

// ---------------- NT fp16 GEMM: 128x256 CTA tile, 64x64 warp tile -----------
// C[m,n] = epi( sum_k A[m,k] * B[n,k] ), f16 inputs, f16 accumulate.
// EPI: 1 = +bias -> f16 ; 2 = exp(alpha*acc) -> f16 ;
//      3 = acc * rowscale[m] * alpha -> f16 ; 4 = acc*alpha + bias + resid -> f32
#define STAGE_ELEMS 15360            // (128+256)*40 f16 per stage
#define GSMEM_BYTES (3*STAGE_ELEMS*2)   // 92160 B

template<int EPI>
__global__ void __launch_bounds__(256)
k_gemm_nt(const f16* __restrict__ Ag, const f16* __restrict__ Bg,
          void* __restrict__ Cg, int M, int N, int K,
          long long sA, long long sB, long long sC,
          const float* __restrict__ bias,
          const float* __restrict__ rowscale, int sRS,
          const float* __restrict__ resid, float alpha)
{
    extern __shared__ f16 dsm[];
    const int tid = threadIdx.x;
    const int bz  = blockIdx.z;
    const f16* A = Ag + (size_t)bz * sA;
    const f16* B = Bg + (size_t)bz * sB;
    const int m0 = blockIdx.y * 128;
    const int n0 = blockIdx.x * 256;
    const int lrow = tid >> 2;
    const int lcol = (tid & 3) << 3;
    const int warp = tid >> 5, lane = tid & 31;
    const int wm = (warp & 1) << 6;
    const int wn = (warp >> 1) << 6;
    const int grp = lane >> 2, qid = lane & 3;

    uint32_t acc[4][8][2];
    #pragma unroll
    for (int i = 0; i < 4; i++)
        #pragma unroll
        for (int j = 0; j < 8; j++){ acc[i][j][0] = 0u; acc[i][j][1] = 0u; }

    const int nkt = K >> 5;

    auto load_stage = [&](int kt, int s){
        const int k0 = kt << 5;
        f16* as_ = dsm + s * STAGE_ELEMS;
        f16* bs_ = as_ + 5120;
        #pragma unroll
        for (int h = 0; h < 2; h++){
            int r = lrow + (h << 6);
            const f16* ga = A + (size_t)(m0 + r) * K + k0 + lcol;
            uint32_t sa = (uint32_t)__cvta_generic_to_shared(&as_[r * 40 + lcol]);
            asm volatile("cp.async.cg.shared.global [%0], [%1], 16;\n" :: "r"(sa), "l"(ga));
        }
        #pragma unroll
        for (int h = 0; h < 4; h++){
            int r = lrow + (h << 6);
            const f16* gb = B + (size_t)(n0 + r) * K + k0 + lcol;
            uint32_t sb = (uint32_t)__cvta_generic_to_shared(&bs_[r * 40 + lcol]);
            asm volatile("cp.async.cg.shared.global [%0], [%1], 16;\n" :: "r"(sb), "l"(gb));
        }
        asm volatile("cp.async.commit_group;\n");
    };

    load_stage(0, 0);
    if (nkt > 1) load_stage(1, 1);

    for (int kt = 0; kt < nkt; kt++){
        const int s = kt % 3;
        if (kt + 1 < nkt) asm volatile("cp.async.wait_group 1;\n");
        else              asm volatile("cp.async.wait_group 0;\n");
        __syncthreads();
        if (kt + 2 < nkt) load_stage(kt + 2, (kt + 2) % 3);

        const f16* as_ = dsm + s * STAGE_ELEMS;
        const f16* bs_ = as_ + 5120;
        #pragma unroll
        for (int ks = 0; ks < 2; ks++){
            const int kk = (ks << 4) + (qid << 1);
            uint32_t af[4][4];
            #pragma unroll
            for (int mi = 0; mi < 4; mi++){
                int r = wm + (mi << 4) + grp;
                af[mi][0] = *(const uint32_t*)&as_[ r      * 40 + kk];
                af[mi][1] = *(const uint32_t*)&as_[(r + 8) * 40 + kk];
                af[mi][2] = *(const uint32_t*)&as_[ r      * 40 + kk + 8];
                af[mi][3] = *(const uint32_t*)&as_[(r + 8) * 40 + kk + 8];
            }
            #pragma unroll
            for (int nj = 0; nj < 8; nj++){
                int r = wn + (nj << 3) + grp;
                uint32_t b0 = *(const uint32_t*)&bs_[r * 40 + kk];
                uint32_t b1 = *(const uint32_t*)&bs_[r * 40 + kk + 8];
                #pragma unroll
                for (int mi = 0; mi < 4; mi++){
                    asm volatile(
                        "mma.sync.aligned.m16n8k16.row.col.f16.f16.f16.f16 "
                        "{%0,%1}, {%2,%3,%4,%5}, {%6,%7}, {%0,%1};\n"
                        : "+r"(acc[mi][nj][0]), "+r"(acc[mi][nj][1])
                        : "r"(af[mi][0]), "r"(af[mi][1]), "r"(af[mi][2]), "r"(af[mi][3]),
                          "r"(b0), "r"(b1));
                }
            }
        }
    }

    #pragma unroll
    for (int mi = 0; mi < 4; mi++){
        #pragma unroll
        for (int nj = 0; nj < 8; nj++){
            int row = m0 + wm + (mi << 4) + grp;
            int col = n0 + wn + (nj << 3) + (qid << 1);
            float2 p0 = __half22float2(*(__half2*)&acc[mi][nj][0]);  // (row, col), (row, col+1)
            float2 p1 = __half22float2(*(__half2*)&acc[mi][nj][1]);  // (row+8, ...)
            float v0 = p0.x, v1 = p0.y, v2 = p1.x, v3 = p1.y;
            if (EPI == 1){
                float b0 = bias[col], b1 = bias[col + 1];
                v0 += b0; v1 += b1; v2 += b0; v3 += b1;
            } else if (EPI == 2){
                v0 = fexp_(v0 * alpha); v1 = fexp_(v1 * alpha);
                v2 = fexp_(v2 * alpha); v3 = fexp_(v3 * alpha);
            } else if (EPI == 3){
                float r0 = rowscale[(size_t)bz * sRS + row] * alpha;
                float r1 = rowscale[(size_t)bz * sRS + row + 8] * alpha;
                v0 *= r0; v1 *= r0; v2 *= r1; v3 *= r1;
            } else if (EPI == 4){
                float b0 = bias[col], b1 = bias[col + 1];
                const float* R0 = resid + (size_t)row * N + col;
                const float* R1 = resid + (size_t)(row + 8) * N + col;
                v0 = v0 * alpha + b0 + R0[0]; v1 = v1 * alpha + b1 + R0[1];
                v2 = v2 * alpha + b0 + R1[0]; v3 = v3 * alpha + b1 + R1[1];
            }
            if (EPI == 4){
                float* C = (float*)Cg + (size_t)bz * sC;
                *(float2*)&C[(size_t)row * N + col]       = make_float2(v0, v1);
                *(float2*)&C[(size_t)(row + 8) * N + col] = make_float2(v2, v3);
            } else {
                f16* C = (f16*)Cg + (size_t)bz * sC;
                *(__half2*)&C[(size_t)row * N + col]       = __floats2half2_rn(v0, v1);
                *(__half2*)&C[(size_t)(row + 8) * N + col] = __floats2half2_rn(v2, v3);
            }
        }
    }
}

// ---------------- launcher --------------------------------------------------
extern "C" void kernel_launch(void* const* d_in, const int* in_sizes, int n_in,
                              void* d_out, int out_size){
    (void)in_sizes; (void)n_in; (void)out_size;
    const float* x_l    = (const float*)d_in[0];
    const float* x_r    = (const float*)d_in[1];
    const float* lp1_w1 = (const float*)d_in[2];
    const float* lp1_b1 = (const float*)d_in[3];
    const float* lp1_w2 = (const float*)d_in[4];
    const float* lp1_b2 = (const float*)d_in[5];
    const float* rp1_w1 = (const float*)d_in[6];
    const float* rp1_b1 = (const float*)d_in[7];
    const float* rp1_w2 = (const float*)d_in[8];
    const float* rp1_b2 = (const float*)d_in[9];
    const float* lp2_w1 = (const float*)d_in[10];
    const float* lp2_b1 = (const float*)d_in[11];
    const float* lp2_w2 = (const float*)d_in[12];
    const float* lp2_b2 = (const float*)d_in[13];
    const float* rp2_w1 = (const float*)d_in[14];
    const float* rp2_b1 = (const float*)d_in[15];
    const float* rp2_w2 = (const float*)d_in[16];
    const float* rp2_b2 = (const float*)d_in[17];
    const float* lp3_w  = (const float*)d_in[18];
    const float* lp3_b  = (const float*)d_in[19];
    const float* rp3_w  = (const float*)d_in[20];
    const float* rp3_b  = (const float*)d_in[21];

    f16 *xhl, *xhr, *w, *H, *Ql, *Qr, *Vt, *VlT, *VrT, *E, *ET, *F1, *F2;
    float *rinv, *cinv;
    cudaGetSymbolAddress((void**)&xhl, g_xhl);
    cudaGetSymbolAddress((void**)&xhr, g_xhr);
    cudaGetSymbolAddress((void**)&w,   g_wts);
    cudaGetSymbolAddress((void**)&H,   g_H);
    cudaGetSymbolAddress((void**)&Ql,  g_Ql);
    cudaGetSymbolAddress((void**)&Qr,  g_Qr);
    cudaGetSymbolAddress((void**)&Vt,  g_Vt);
    cudaGetSymbolAddress((void**)&VlT, g_VlT);
    cudaGetSymbolAddress((void**)&VrT, g_VrT);
    cudaGetSymbolAddress((void**)&E,   g_E);
    cudaGetSymbolAddress((void**)&ET,  g_ET);
    cudaGetSymbolAddress((void**)&F1,  g_F1);
    cudaGetSymbolAddress((void**)&F2,  g_F2);
    cudaGetSymbolAddress((void**)&rinv, g_rinv);
    cudaGetSymbolAddress((void**)&cinv, g_cinv);

    cudaFuncSetAttribute(k_gemm_nt<1>, cudaFuncAttributeMaxDynamicSharedMemorySize, GSMEM_BYTES);
    cudaFuncSetAttribute(k_gemm_nt<2>, cudaFuncAttributeMaxDynamicSharedMemorySize, GSMEM_BYTES);
    cudaFuncSetAttribute(k_gemm_nt<3>, cudaFuncAttributeMaxDynamicSharedMemorySize, GSMEM_BYTES);
    cudaFuncSetAttribute(k_gemm_nt<4>, cudaFuncAttributeMaxDynamicSharedMemorySize, GSMEM_BYTES);

    const int nx = NX, nw = NW;
    const float scale  = 0.04419417382415922f;   // 512^-0.5
    const float FSC    = 64.0f;                  // F magnitude boost (subnormal guard)
    const float FSCINV = 1.0f / 64.0f;

    dim3 blk(256);
    dim3 gP(NC/256, (NB*NT)/128, 1);     // (2,128,1)
    dim3 gA(NT/256, NT/128, NB);         // (8,16,8)
    dim3 gF(NC/256, NT/128, NB);         // (2,16,8)
    dim3 gTv(NC/64, NT/64, NB);
    dim3 gTe(NT/64, NT/64, NB);
    const int dwBlocks = (NX/2)/256;

    // launches 1-5: converts needed for the first GEMM
    k_f2h<<<nx/1024, 256>>>(x_l, xhl, nx);
    k_f2h<<<nx/1024, 256>>>(x_r, xhr, nx);
    k_f2h<<<nw/1024, 256>>>(lp1_w1, w + 0*nw, nw);
    k_f2h<<<nw/1024, 256>>>(rp1_w1, w + 1*nw, nw);
    k_f2h<<<nw/1024, 256>>>(lp2_w1, w + 2*nw, nw);

    // launch 6 (profiled by ncu -s 5 -c 1): projection GEMM
    k_gemm_nt<1><<<gP, blk, GSMEM_BYTES>>>(xhl, w + 0*nw, H, NB*NT, NC, NC, 0,0,0, lp1_b1, nullptr,0, nullptr, 0.f);
    k_dw<<<dwBlocks, 256>>>(H, lp1_w2, lp1_b2, Ql);

    // remaining converts
    k_f2h<<<nw/1024, 256>>>(rp2_w1, w + 3*nw, nw);
    k_f2h<<<nw/1024, 256>>>(lp3_w,  w + 4*nw, nw);
    k_f2h<<<nw/1024, 256>>>(rp3_w,  w + 5*nw, nw);

    // projections -> Q_r, V_lT, V_rT
    k_gemm_nt<1><<<gP, blk, GSMEM_BYTES>>>(xhr, w + 1*nw, H, NB*NT, NC, NC, 0,0,0, rp1_b1, nullptr,0, nullptr, 0.f);
    k_dw<<<dwBlocks, 256>>>(H, rp1_w2, rp1_b2, Qr);
    k_gemm_nt<1><<<gP, blk, GSMEM_BYTES>>>(xhl, w + 2*nw, H, NB*NT, NC, NC, 0,0,0, lp2_b1, nullptr,0, nullptr, 0.f);
    k_dw<<<dwBlocks, 256>>>(H, lp2_w2, lp2_b2, Vt);
    k_transpose<<<gTv, 256>>>(Vt, VlT, NT, NC);
    k_gemm_nt<1><<<gP, blk, GSMEM_BYTES>>>(xhr, w + 3*nw, H, NB*NT, NC, NC, 0,0,0, rp2_b1, nullptr,0, nullptr, 0.f);
    k_dw<<<dwBlocks, 256>>>(H, rp2_w2, rp2_b2, Vt);
    k_transpose<<<gTv, 256>>>(Vt, VrT, NT, NC);

    // E = exp(scale * Q_l Q_r^T)
    k_gemm_nt<2><<<gA, blk, GSMEM_BYTES>>>(Ql, Qr, E, NT, NT, NC,
                              (long long)NT*NC, (long long)NT*NC, (long long)NT*NT,
                              nullptr, nullptr, 0, nullptr, scale);

    // softmax denominators
    k_rowsum_inv<<<NB*NT, 256>>>(E, rinv, NT);
    k_transpose<<<gTe, 256>>>(E, ET, NT, NT);
    k_rowsum_inv<<<NB*NT, 256>>>(ET, cinv, NT);

    // attention applies; F scaled up by 64 (kept normal in f16), undone in EPI=4
    k_gemm_nt<3><<<gF, blk, GSMEM_BYTES>>>(E, VrT, F1, NT, NC, NT,
                              (long long)NT*NT, (long long)NC*NT, (long long)NT*NC,
                              nullptr, rinv, NT, nullptr, FSC);
    k_gemm_nt<3><<<gF, blk, GSMEM_BYTES>>>(ET, VlT, F2, NT, NC, NT,
                              (long long)NT*NT, (long long)NC*NT, (long long)NT*NC,
                              nullptr, cinv, NT, nullptr, FSC);

    // output projections + residual -> fp32 out
    float* out = (float*)d_out;
    k_gemm_nt<4><<<gP, blk, GSMEM_BYTES>>>(F1, w + 4*nw, out,      NB*NT, NC, NC, 0,0,0, lp3_b, nullptr,0, x_l, FSCINV);
    k_gemm_nt<4><<<gP, blk, GSMEM_BYTES>>>(F2, w + 5*nw, out + nx, NB*NT, NC, NC, 0,0,0, rp3_b, nullptr,0, x_r, FSCINV);
}